// round 12
// baseline (speedup 1.0000x reference)
#include <cuda_runtime.h>
#include <cuda_fp16.h>
#include <cstdint>

#define NROWS 4096
#define INDIM 1024
#define DDIM  2048
#define TWOD  4096
#define NGATE 8
#define OUTDIM 1024
#define W1R   (2*(1+NGATE)*DDIM)   // 36864

// ---------------------------------------------------------------------------
// Device scratch (allocation-free rule: __device__ globals)
// A-side operands are split fp16 hi/lo; weights are single fp16.
// ---------------------------------------------------------------------------
__device__ __half g_xh [(size_t)NROWS * INDIM];
__device__ __half g_xl [(size_t)NROWS * INDIM];
__device__ __half g_W1f[(size_t)W1R   * INDIM];
__device__ __half g_W2f[(size_t)DDIM  * TWOD];
__device__ __half g_W3f[(size_t)OUTDIM* DDIM];
__device__ __half g_sh [(size_t)NROWS * TWOD];
__device__ __half g_sl [(size_t)NROWS * TWOD];
__device__ __half g_h2h[(size_t)NROWS * DDIM];
__device__ __half g_h2l[(size_t)NROWS * DDIM];
__device__ int g_perm[NROWS];
__device__ int g_off[NGATE + 1];

// ---------------------------------------------------------------------------
__global__ void sort_gates(const int* __restrict__ gate_ids) {
    __shared__ int cnt[NGATE];
    __shared__ int base[NGATE];
    int t = threadIdx.x;
    if (t < NGATE) cnt[t] = 0;
    __syncthreads();
    for (int i = t; i < NROWS; i += blockDim.x)
        atomicAdd(&cnt[gate_ids[i]], 1);
    __syncthreads();
    if (t == 0) {
        int a = 0;
        for (int g = 0; g < NGATE; g++) { base[g] = a; g_off[g] = a; a += cnt[g]; }
        g_off[NGATE] = a;
    }
    __syncthreads();
    for (int i = t; i < NROWS; i += blockDim.x) {
        int g = gate_ids[i];
        int p = atomicAdd(&base[g], 1);
        g_perm[p] = i;
    }
}

// ---------------------------------------------------------------------------
// fp32 -> (fp16 hi, fp16 lo) exact split (activations)
// ---------------------------------------------------------------------------
__global__ __launch_bounds__(256) void split_f32h(
    const float* __restrict__ in,
    __half* __restrict__ hi, __half* __restrict__ lo, int n4)
{
    int i = blockIdx.x * 256 + threadIdx.x;
    if (i >= n4) return;
    float4 v = reinterpret_cast<const float4*>(in)[i];
    __half h0 = __float2half_rn(v.x);
    __half h1 = __float2half_rn(v.y);
    __half h2 = __float2half_rn(v.z);
    __half h3 = __float2half_rn(v.w);
    __half l0 = __float2half_rn(v.x - __half2float(h0));
    __half l1 = __float2half_rn(v.y - __half2float(h1));
    __half l2 = __float2half_rn(v.z - __half2float(h2));
    __half l3 = __float2half_rn(v.w - __half2float(h3));
    reinterpret_cast<ushort4*>(hi)[i] = make_ushort4(
        __half_as_ushort(h0), __half_as_ushort(h1),
        __half_as_ushort(h2), __half_as_ushort(h3));
    reinterpret_cast<ushort4*>(lo)[i] = make_ushort4(
        __half_as_ushort(l0), __half_as_ushort(l1),
        __half_as_ushort(l2), __half_as_ushort(l3));
}

// fp32 -> fp16 (weights, single rounding)
__global__ __launch_bounds__(256) void conv_f32h(
    const float* __restrict__ in, __half* __restrict__ outp, int n4)
{
    int i = blockIdx.x * 256 + threadIdx.x;
    if (i >= n4) return;
    float4 v = reinterpret_cast<const float4*>(in)[i];
    reinterpret_cast<ushort4*>(outp)[i] = make_ushort4(
        __half_as_ushort(__float2half_rn(v.x)),
        __half_as_ushort(__float2half_rn(v.y)),
        __half_as_ushort(__float2half_rn(v.z)),
        __half_as_ushort(__float2half_rn(v.w)));
}

// ---------------------------------------------------------------------------
// Helpers (portable to base sm_103: mma.sync + cp.async + ldmatrix)
// ---------------------------------------------------------------------------
__device__ __forceinline__ uint32_t smem_u32(const void* p) {
    uint32_t a;
    asm("{ .reg .u64 t; cvta.to.shared.u64 t, %1; cvt.u32.u64 %0, t; }"
        : "=r"(a) : "l"(p));
    return a;
}
__device__ __forceinline__ void cp16(uint32_t dst, const void* src, bool pred) {
    int sz = pred ? 16 : 0;
    asm volatile("cp.async.cg.shared.global [%0], [%1], 16, %2;"
                 :: "r"(dst), "l"(src), "r"(sz) : "memory");
}
__device__ __forceinline__ void mma16816(float* c, const uint32_t* a,
                                         const uint32_t* b) {
    asm volatile(
        "mma.sync.aligned.m16n8k16.row.col.f32.f16.f16.f32 "
        "{%0,%1,%2,%3}, {%4,%5,%6,%7}, {%8,%9}, {%0,%1,%2,%3};"
        : "+f"(c[0]), "+f"(c[1]), "+f"(c[2]), "+f"(c[3])
        : "r"(a[0]), "r"(a[1]), "r"(a[2]), "r"(a[3]), "r"(b[0]), "r"(b[1]));
}
__device__ __forceinline__ void ldsm4(uint32_t* r, uint32_t addr) {
    asm volatile("ldmatrix.sync.aligned.m8n8.x4.shared.b16 {%0,%1,%2,%3}, [%4];"
                 : "=r"(r[0]), "=r"(r[1]), "=r"(r[2]), "=r"(r[3]) : "r"(addr));
}

constexpr int BM = 128, BN = 128, BK = 32;
constexpr int ROWB  = BK * 2;            // 64 bytes per smem row
constexpr int ARR   = BM * ROWB;         // 8KB per array (Ah/Al/Bf)
constexpr int STAGE = 3 * ARR;           // 24KB
constexpr int NST   = 3;
constexpr int SMEM_TOTAL = NST * STAGE;  // 72KB -> 2 CTAs/SM
constexpr int THREADS = 128;             // 4 warps, 2x2, 64x64 warp tiles

// swizzle: 16B slot XOR'd by (row>>1)&3 — conflict-free for ldmatrix 8-row
// groups. XOR applied to the FINAL column (incl. K-half offset): no carry.
__device__ __forceinline__ uint32_t swz_off(uint32_t row, uint32_t col) {
    return row * ROWB + (col ^ (((row >> 1) & 3u) << 4));
}

// ---------------------------------------------------------------------------
// fp16x2 GEMM on mma.sync + ldmatrix:
//   Out[m,n] = epi( (Ah+Al)[m,:].Wf[n,:] + bias )   -- 2 MMAs per fragment
// Epilogue: +bias, relu, *scale, += (addH+addL), fp32 store OR fp16 hi/lo split.
// GATE: rows gathered/scattered via g_perm segment blockIdx.z, W offset by gate.
// ---------------------------------------------------------------------------
template<bool GATE>
__global__ __launch_bounds__(THREADS, 2)
void mma_gemm(const __half* __restrict__ Ah,
              const __half* __restrict__ Al,
              const __half* __restrict__ Wf_,
              const float* __restrict__ bias_,
              float* __restrict__ outF,
              __half* __restrict__ outH, __half* __restrict__ outL,
              const __half* __restrict__ addH,
              const __half* __restrict__ addL,
              int Nout, int K, int do_relu, float scale)
{
    extern __shared__ char smem[];
    const uint32_t sb = smem_u32(smem);
    const int tid = threadIdx.x, wid = tid >> 5, lid = tid & 31;

    int rowStart, rowValid;
    const __half* Wf = Wf_;
    const float* bp = bias_;
    if (GATE) {
        int g = blockIdx.z;
        int s0 = g_off[g], s1 = g_off[g + 1];
        rowStart = s0 + blockIdx.y * BM;
        if (rowStart >= s1) return;
        rowValid = min(BM, s1 - rowStart);
        Wf += (size_t)g * Nout * K;
        if (bp) bp += (size_t)g * Nout;
    } else {
        rowStart = blockIdx.y * BM;
        rowValid = BM;
    }
    const int cb = blockIdx.x * BN;

    // ---- cp.async mapping: 128 threads x 4 iters cover 512 chunks per array
    const __half* pAh[4];
    const __half* pAl[4];
    const __half* pBf[4];
    bool vA[4];
    uint32_t dOf[4];
#pragma unroll
    for (int i = 0; i < 4; i++) {
        int cid = tid + i * THREADS;
        int r = cid >> 2, c16 = cid & 3;
        dOf[i] = swz_off(r, c16 * 16);
        int ar;
        if (GATE) { ar = (r < rowValid) ? g_perm[rowStart + r] : -1; }
        else      { ar = rowStart + r; }
        vA[i] = ar >= 0;
        size_t aoff = (vA[i] ? (size_t)ar * K : 0) + c16 * 8;
        pAh[i] = Ah + aoff;
        pAl[i] = Al + aoff;
        pBf[i] = Wf + (size_t)(cb + r) * K + c16 * 8;
    }

    const int T = K / BK;
    auto load_tile = [&](int kt) {
        uint32_t st = sb + (kt % NST) * STAGE;
        int ke = kt * BK;
#pragma unroll
        for (int i = 0; i < 4; i++) {
            cp16(st + 0 * ARR + dOf[i], pAh[i] + ke, vA[i]);
            cp16(st + 1 * ARR + dOf[i], pAl[i] + ke, vA[i]);
            cp16(st + 2 * ARR + dOf[i], pBf[i] + ke, true);
        }
        asm volatile("cp.async.commit_group;" ::: "memory");
    };

    float acc[4][8][4];
#pragma unroll
    for (int a = 0; a < 4; a++)
#pragma unroll
        for (int b = 0; b < 8; b++)
#pragma unroll
            for (int c = 0; c < 4; c++) acc[a][b][c] = 0.f;

    // warp tiling: 2x2 warps, 64x64 per warp
    const int wm = (wid >> 1) * 64;
    const int wn = (wid & 1) * 64;
    const int lg = lid >> 3, l7 = lid & 7;

    // ldmatrix lane components: row offset + mask separate from column so the
    // K-half offset is added BEFORE the swizzle XOR (no carry into row bits).
    uint32_t rowA[4], mskA[4], rowB[4], mskB[4];
    const uint32_t colA = (uint32_t)(lg >> 1) << 4;
    const uint32_t colB = (uint32_t)(lg & 1) << 4;
#pragma unroll
    for (int mt = 0; mt < 4; mt++) {
        uint32_t row = wm + mt * 16 + ((lg & 1) << 3) + l7;
        rowA[mt] = row * ROWB;
        mskA[mt] = ((row >> 1) & 3u) << 4;
    }
#pragma unroll
    for (int np = 0; np < 4; np++) {
        uint32_t row = wn + np * 16 + ((lg >> 1) << 3) + l7;
        rowB[np] = row * ROWB;
        mskB[np] = ((row >> 1) & 3u) << 4;
    }

    load_tile(0);
    load_tile(1);

    for (int kt = 0; kt < T; kt++) {
        if (kt < T - 1) asm volatile("cp.async.wait_group 1;" ::: "memory");
        else            asm volatile("cp.async.wait_group 0;" ::: "memory");
        __syncthreads();
        if (kt + 2 < T) load_tile(kt + 2);

        const uint32_t S = sb + (kt % NST) * STAGE;
#pragma unroll
        for (int kh = 0; kh < 2; kh++) {
            const uint32_t kof = kh * 32;
            uint32_t ah[4][4], al[4][4], bf[4][4];
#pragma unroll
            for (int mt = 0; mt < 4; mt++) {
                uint32_t off = rowA[mt] + ((colA + kof) ^ mskA[mt]);
                ldsm4(ah[mt], S + 0 * ARR + off);
                ldsm4(al[mt], S + 1 * ARR + off);
            }
#pragma unroll
            for (int np = 0; np < 4; np++) {
                uint32_t off = rowB[np] + ((colB + kof) ^ mskB[np]);
                ldsm4(bf[np], S + 2 * ARR + off);
            }
#pragma unroll
            for (int mt = 0; mt < 4; mt++) {
#pragma unroll
                for (int np = 0; np < 4; np++) {
                    // np covers nt = 2np (regs 0,1) and nt = 2np+1 (regs 2,3)
                    mma16816(acc[mt][2 * np],     ah[mt], &bf[np][0]);
                    mma16816(acc[mt][2 * np],     al[mt], &bf[np][0]);
                    mma16816(acc[mt][2 * np + 1], ah[mt], &bf[np][2]);
                    mma16816(acc[mt][2 * np + 1], al[mt], &bf[np][2]);
                }
            }
        }
    }

    // ------------------------------- epilogue ------------------------------
    const int gr = lid >> 2;
#pragma unroll
    for (int mt = 0; mt < 4; mt++) {
#pragma unroll
        for (int half = 0; half < 2; half++) {
            const int rloc = wm + mt * 16 + gr + half * 8;
            int grow;
            bool valid = true;
            if (GATE) {
                valid = (rloc < rowValid);
                grow = valid ? g_perm[rowStart + rloc] : 0;
            } else {
                grow = rowStart + rloc;
            }
            if (!valid) continue;
#pragma unroll
            for (int nt = 0; nt < 8; nt++) {
                const int col = cb + wn + nt * 8 + (lid & 3) * 2;
                float v0 = acc[mt][nt][half * 2 + 0];
                float v1 = acc[mt][nt][half * 2 + 1];
                if (bp) {
                    float2 bb = *(const float2*)(bp + col);
                    v0 += bb.x; v1 += bb.y;
                }
                if (do_relu) { v0 = fmaxf(v0, 0.f); v1 = fmaxf(v1, 0.f); }
                v0 *= scale; v1 *= scale;
                const size_t rb = (size_t)grow * Nout + col;
                if (addH) {
                    uint32_t uh = *(const uint32_t*)(addH + rb);
                    uint32_t ul = *(const uint32_t*)(addL + rb);
                    float2 fh = __half22float2(
                        *reinterpret_cast<__half2*>(&uh));
                    float2 fl = __half22float2(
                        *reinterpret_cast<__half2*>(&ul));
                    v0 += fh.x + fl.x; v1 += fh.y + fl.y;
                }
                if (outF) {
                    *(float2*)(outF + rb) = make_float2(v0, v1);
                } else {
                    __half h0 = __float2half_rn(v0);
                    __half h1 = __float2half_rn(v1);
                    __half l0 = __float2half_rn(v0 - __half2float(h0));
                    __half l1 = __float2half_rn(v1 - __half2float(h1));
                    uint32_t ph = (uint32_t)__half_as_ushort(h0) |
                                  ((uint32_t)__half_as_ushort(h1) << 16);
                    uint32_t pl = (uint32_t)__half_as_ushort(l0) |
                                  ((uint32_t)__half_as_ushort(l1) << 16);
                    *(uint32_t*)(outH + rb) = ph;
                    *(uint32_t*)(outL + rb) = pl;
                }
            }
        }
    }
}

// ---------------------------------------------------------------------------
extern "C" void kernel_launch(void* const* d_in, const int* in_sizes, int n_in,
                              void* d_out, int out_size) {
    const float* x   = (const float*)d_in[0];
    const int*   gid = (const int*)  d_in[1];
    const float* W1  = (const float*)d_in[2];
    const float* b1  = (const float*)d_in[3];
    const float* W2  = (const float*)d_in[4];
    const float* b2  = (const float*)d_in[5];
    const float* W3  = (const float*)d_in[6];
    float* out = (float*)d_out;

    __half *xh, *xl, *w1f, *w2f, *w3f, *sh, *sl, *h2h, *h2l;
    cudaGetSymbolAddress((void**)&xh,  g_xh);  cudaGetSymbolAddress((void**)&xl,  g_xl);
    cudaGetSymbolAddress((void**)&w1f, g_W1f);
    cudaGetSymbolAddress((void**)&w2f, g_W2f);
    cudaGetSymbolAddress((void**)&w3f, g_W3f);
    cudaGetSymbolAddress((void**)&sh,  g_sh);  cudaGetSymbolAddress((void**)&sl,  g_sl);
    cudaGetSymbolAddress((void**)&h2h, g_h2h); cudaGetSymbolAddress((void**)&h2l, g_h2l);

    cudaFuncSetAttribute((const void*)mma_gemm<true>,
                         cudaFuncAttributeMaxDynamicSharedMemorySize, SMEM_TOTAL);
    cudaFuncSetAttribute((const void*)mma_gemm<false>,
                         cudaFuncAttributeMaxDynamicSharedMemorySize, SMEM_TOTAL);

    sort_gates<<<1, 256>>>(gid);

    auto nblk = [](size_t elems) { return (int)((elems / 4 + 255) / 256); };
    split_f32h<<<nblk((size_t)NROWS * INDIM), 256>>>(x, xh, xl, NROWS * INDIM / 4);
    conv_f32h<<<nblk((size_t)W1R * INDIM),   256>>>(W1, w1f, (int)((size_t)W1R * INDIM / 4));
    conv_f32h<<<nblk((size_t)DDIM * TWOD),   256>>>(W2, w2f, DDIM * TWOD / 4);
    conv_f32h<<<nblk((size_t)OUTDIM * DDIM), 256>>>(W3, w3f, OUTDIM * DDIM / 4);

    // L1 gate blocks: s = 0.9*relu(x @ W1_g^T + b1_g), rows scattered via perm
    mma_gemm<true><<<dim3(TWOD / BN, NROWS / BM, NGATE), THREADS, SMEM_TOTAL>>>(
        xh, xl, w1f, b1,
        nullptr, sh, sl, nullptr, nullptr,
        TWOD, INDIM, /*relu=*/1, /*scale=*/0.9f);

    // L1 shared block: s += relu(x @ W1_sh^T + b1_sh)  (adds prior s, re-splits)
    mma_gemm<false><<<dim3(TWOD / BN, NROWS / BM), THREADS, SMEM_TOTAL>>>(
        xh, xl,
        w1f + (size_t)NGATE * TWOD * INDIM,
        b1 + (size_t)NGATE * TWOD,
        nullptr, sh, sl, sh, sl,
        TWOD, INDIM, /*relu=*/1, /*scale=*/1.0f);

    // L2: h2 = relu(s @ W2^T + b2)
    mma_gemm<false><<<dim3(DDIM / BN, NROWS / BM), THREADS, SMEM_TOTAL>>>(
        sh, sl, w2f, b2,
        nullptr, h2h, h2l, nullptr, nullptr,
        DDIM, TWOD, /*relu=*/1, /*scale=*/1.0f);

    // L3: out = h2 @ W3^T  (fp32 store)
    mma_gemm<false><<<dim3(OUTDIM / BN, NROWS / BM), THREADS, SMEM_TOTAL>>>(
        h2h, h2l, w3f, nullptr,
        out, nullptr, nullptr, nullptr, nullptr,
        OUTDIM, DDIM, /*relu=*/0, /*scale=*/1.0f);
}

// round 13
// speedup vs baseline: 1.9252x; 1.9252x over previous
#include <cuda_runtime.h>
#include <cuda_fp16.h>
#include <cstdint>

#define NROWS 4096
#define INDIM 1024
#define DDIM  2048
#define TWOD  4096
#define NGATE 8
#define OUTDIM 1024
#define W1R   (2*(1+NGATE)*DDIM)   // 36864

// ---------------------------------------------------------------------------
// Device scratch (allocation-free rule: __device__ globals). Everything fp16.
// ---------------------------------------------------------------------------
__device__ __half g_xf [(size_t)NROWS * INDIM];
__device__ __half g_W1f[(size_t)W1R   * INDIM];
__device__ __half g_W2f[(size_t)DDIM  * TWOD];
__device__ __half g_W3f[(size_t)OUTDIM* DDIM];
__device__ __half g_sf [(size_t)NROWS * TWOD];
__device__ __half g_h2f[(size_t)NROWS * DDIM];
__device__ int g_perm[NROWS];
__device__ int g_off[NGATE + 1];

// ---------------------------------------------------------------------------
__global__ void sort_gates(const int* __restrict__ gate_ids) {
    __shared__ int cnt[NGATE];
    __shared__ int base[NGATE];
    int t = threadIdx.x;
    if (t < NGATE) cnt[t] = 0;
    __syncthreads();
    for (int i = t; i < NROWS; i += blockDim.x)
        atomicAdd(&cnt[gate_ids[i]], 1);
    __syncthreads();
    if (t == 0) {
        int a = 0;
        for (int g = 0; g < NGATE; g++) { base[g] = a; g_off[g] = a; a += cnt[g]; }
        g_off[NGATE] = a;
    }
    __syncthreads();
    for (int i = t; i < NROWS; i += blockDim.x) {
        int g = gate_ids[i];
        int p = atomicAdd(&base[g], 1);
        g_perm[p] = i;
    }
}

// ---------------------------------------------------------------------------
// fp32 -> fp16, 4 independent float4 loads per thread (MLP=4)
// ---------------------------------------------------------------------------
__global__ __launch_bounds__(256) void conv_f32h(
    const float* __restrict__ in, __half* __restrict__ outp, int n4)
{
    int base = blockIdx.x * 1024 + threadIdx.x;
    float4 v[4];
    bool ok[4];
#pragma unroll
    for (int j = 0; j < 4; j++) {
        int idx = base + j * 256;
        ok[j] = idx < n4;
        if (ok[j]) v[j] = reinterpret_cast<const float4*>(in)[idx];
    }
#pragma unroll
    for (int j = 0; j < 4; j++) {
        if (!ok[j]) continue;
        int idx = base + j * 256;
        reinterpret_cast<ushort4*>(outp)[idx] = make_ushort4(
            __half_as_ushort(__float2half_rn(v[j].x)),
            __half_as_ushort(__float2half_rn(v[j].y)),
            __half_as_ushort(__float2half_rn(v[j].z)),
            __half_as_ushort(__float2half_rn(v[j].w)));
    }
}

// ---------------------------------------------------------------------------
// Helpers (portable to base sm_103: mma.sync + cp.async + ldmatrix)
// ---------------------------------------------------------------------------
__device__ __forceinline__ uint32_t smem_u32(const void* p) {
    uint32_t a;
    asm("{ .reg .u64 t; cvta.to.shared.u64 t, %1; cvt.u32.u64 %0, t; }"
        : "=r"(a) : "l"(p));
    return a;
}
__device__ __forceinline__ void cp16(uint32_t dst, const void* src, bool pred) {
    int sz = pred ? 16 : 0;
    asm volatile("cp.async.cg.shared.global [%0], [%1], 16, %2;"
                 :: "r"(dst), "l"(src), "r"(sz) : "memory");
}
__device__ __forceinline__ void mma16816(float* c, const uint32_t* a,
                                         const uint32_t* b) {
    asm volatile(
        "mma.sync.aligned.m16n8k16.row.col.f32.f16.f16.f32 "
        "{%0,%1,%2,%3}, {%4,%5,%6,%7}, {%8,%9}, {%0,%1,%2,%3};"
        : "+f"(c[0]), "+f"(c[1]), "+f"(c[2]), "+f"(c[3])
        : "r"(a[0]), "r"(a[1]), "r"(a[2]), "r"(a[3]), "r"(b[0]), "r"(b[1]));
}
__device__ __forceinline__ void ldsm4(uint32_t* r, uint32_t addr) {
    asm volatile("ldmatrix.sync.aligned.m8n8.x4.shared.b16 {%0,%1,%2,%3}, [%4];"
                 : "=r"(r[0]), "=r"(r[1]), "=r"(r[2]), "=r"(r[3]) : "r"(addr));
}

constexpr int BM = 128, BN = 128, BK = 32;
constexpr int ROWB  = BK * 2;            // 64 bytes per smem row
constexpr int ARR   = BM * ROWB;         // 8KB per array (Af / Bf)
constexpr int STAGE = 2 * ARR;           // 16KB
constexpr int NST   = 4;
constexpr int SMEM_TOTAL = NST * STAGE;  // 64KB -> 2 CTAs/SM
constexpr int THREADS = 128;             // 4 warps, 2x2, 64x64 warp tiles

// swizzle: 16B slot XOR'd by (row>>1)&3 — conflict-free for ldmatrix 8-row
// groups. XOR applied to the FINAL column (incl. K-half offset): no carry.
__device__ __forceinline__ uint32_t swz_off(uint32_t row, uint32_t col) {
    return row * ROWB + (col ^ (((row >> 1) & 3u) << 4));
}

// ---------------------------------------------------------------------------
// fp16 GEMM on mma.sync + ldmatrix: Out[m,n] = epi( Af[m,:].Wf[n,:] + bias )
// Epilogue: +bias, relu, *scale, += addH, fp32 store OR fp16 store.
// GATE: rows gathered/scattered via g_perm segment blockIdx.z, W offset by gate.
// ---------------------------------------------------------------------------
template<bool GATE>
__global__ __launch_bounds__(THREADS, 2)
void mma_gemm(const __half* __restrict__ Af,
              const __half* __restrict__ Wf_,
              const float* __restrict__ bias_,
              float* __restrict__ outF,
              __half* __restrict__ outH,
              const __half* __restrict__ addH,
              int Nout, int K, int do_relu, float scale)
{
    extern __shared__ char smem[];
    const uint32_t sb = smem_u32(smem);
    const int tid = threadIdx.x, wid = tid >> 5, lid = tid & 31;

    int rowStart, rowValid;
    const __half* Wf = Wf_;
    const float* bp = bias_;
    if (GATE) {
        int g = blockIdx.z;
        int s0 = g_off[g], s1 = g_off[g + 1];
        rowStart = s0 + blockIdx.y * BM;
        if (rowStart >= s1) return;
        rowValid = min(BM, s1 - rowStart);
        Wf += (size_t)g * Nout * K;
        if (bp) bp += (size_t)g * Nout;
    } else {
        rowStart = blockIdx.y * BM;
        rowValid = BM;
    }
    const int cb = blockIdx.x * BN;

    // ---- cp.async mapping: 128 threads x 4 iters cover 512 chunks per array
    const __half* pAf[4];
    const __half* pBf[4];
    bool vA[4];
    uint32_t dOf[4];
#pragma unroll
    for (int i = 0; i < 4; i++) {
        int cid = tid + i * THREADS;
        int r = cid >> 2, c16 = cid & 3;
        dOf[i] = swz_off(r, c16 * 16);
        int ar;
        if (GATE) { ar = (r < rowValid) ? g_perm[rowStart + r] : -1; }
        else      { ar = rowStart + r; }
        vA[i] = ar >= 0;
        pAf[i] = Af + (vA[i] ? (size_t)ar * K : 0) + c16 * 8;
        pBf[i] = Wf + (size_t)(cb + r) * K + c16 * 8;
    }

    const int T = K / BK;
    auto load_tile = [&](int kt) {
        uint32_t st = sb + (kt % NST) * STAGE;
        int ke = kt * BK;
#pragma unroll
        for (int i = 0; i < 4; i++) {
            cp16(st + 0 * ARR + dOf[i], pAf[i] + ke, vA[i]);
            cp16(st + 1 * ARR + dOf[i], pBf[i] + ke, true);
        }
        asm volatile("cp.async.commit_group;" ::: "memory");
    };

    float acc[4][8][4];
#pragma unroll
    for (int a = 0; a < 4; a++)
#pragma unroll
        for (int b = 0; b < 8; b++)
#pragma unroll
            for (int c = 0; c < 4; c++) acc[a][b][c] = 0.f;

    // warp tiling: 2x2 warps, 64x64 per warp
    const int wm = (wid >> 1) * 64;
    const int wn = (wid & 1) * 64;
    const int lg = lid >> 3, l7 = lid & 7;

    // ldmatrix lane components: row offset + mask separate from column so the
    // K-half offset is added BEFORE the swizzle XOR (no carry into row bits).
    uint32_t rowA[4], mskA[4], rowB[4], mskB[4];
    const uint32_t colA = (uint32_t)(lg >> 1) << 4;
    const uint32_t colB = (uint32_t)(lg & 1) << 4;
#pragma unroll
    for (int mt = 0; mt < 4; mt++) {
        uint32_t row = wm + mt * 16 + ((lg & 1) << 3) + l7;
        rowA[mt] = row * ROWB;
        mskA[mt] = ((row >> 1) & 3u) << 4;
    }
#pragma unroll
    for (int np = 0; np < 4; np++) {
        uint32_t row = wn + np * 16 + ((lg >> 1) << 3) + l7;
        rowB[np] = row * ROWB;
        mskB[np] = ((row >> 1) & 3u) << 4;
    }

    load_tile(0);
    load_tile(1);
    load_tile(2);

    for (int kt = 0; kt < T; kt++) {
        if (kt < T - 2)      asm volatile("cp.async.wait_group 2;" ::: "memory");
        else if (kt == T - 2) asm volatile("cp.async.wait_group 1;" ::: "memory");
        else                 asm volatile("cp.async.wait_group 0;" ::: "memory");
        __syncthreads();
        if (kt + 3 < T) load_tile(kt + 3);

        const uint32_t S = sb + (kt % NST) * STAGE;
#pragma unroll
        for (int kh = 0; kh < 2; kh++) {
            const uint32_t kof = kh * 32;
            uint32_t af[4][4], bf[4][4];
#pragma unroll
            for (int mt = 0; mt < 4; mt++) {
                uint32_t off = rowA[mt] + ((colA + kof) ^ mskA[mt]);
                ldsm4(af[mt], S + 0 * ARR + off);
            }
#pragma unroll
            for (int np = 0; np < 4; np++) {
                uint32_t off = rowB[np] + ((colB + kof) ^ mskB[np]);
                ldsm4(bf[np], S + 1 * ARR + off);
            }
#pragma unroll
            for (int mt = 0; mt < 4; mt++) {
#pragma unroll
                for (int np = 0; np < 4; np++) {
                    // np covers nt = 2np (regs 0,1) and nt = 2np+1 (regs 2,3)
                    mma16816(acc[mt][2 * np],     af[mt], &bf[np][0]);
                    mma16816(acc[mt][2 * np + 1], af[mt], &bf[np][2]);
                }
            }
        }
    }

    // ------------------------------- epilogue ------------------------------
    const int gr = lid >> 2;
#pragma unroll
    for (int mt = 0; mt < 4; mt++) {
#pragma unroll
        for (int half = 0; half < 2; half++) {
            const int rloc = wm + mt * 16 + gr + half * 8;
            int grow;
            bool valid = true;
            if (GATE) {
                valid = (rloc < rowValid);
                grow = valid ? g_perm[rowStart + rloc] : 0;
            } else {
                grow = rowStart + rloc;
            }
            if (!valid) continue;
#pragma unroll
            for (int nt = 0; nt < 8; nt++) {
                const int col = cb + wn + nt * 8 + (lid & 3) * 2;
                float v0 = acc[mt][nt][half * 2 + 0];
                float v1 = acc[mt][nt][half * 2 + 1];
                if (bp) {
                    float2 bb = *(const float2*)(bp + col);
                    v0 += bb.x; v1 += bb.y;
                }
                if (do_relu) { v0 = fmaxf(v0, 0.f); v1 = fmaxf(v1, 0.f); }
                v0 *= scale; v1 *= scale;
                const size_t rb = (size_t)grow * Nout + col;
                if (addH) {
                    uint32_t uh = *(const uint32_t*)(addH + rb);
                    float2 fh = __half22float2(*reinterpret_cast<__half2*>(&uh));
                    v0 += fh.x; v1 += fh.y;
                }
                if (outF) {
                    *(float2*)(outF + rb) = make_float2(v0, v1);
                } else {
                    uint32_t ph = (uint32_t)__half_as_ushort(__float2half_rn(v0)) |
                                  ((uint32_t)__half_as_ushort(__float2half_rn(v1)) << 16);
                    *(uint32_t*)(outH + rb) = ph;
                }
            }
        }
    }
}

// ---------------------------------------------------------------------------
extern "C" void kernel_launch(void* const* d_in, const int* in_sizes, int n_in,
                              void* d_out, int out_size) {
    const float* x   = (const float*)d_in[0];
    const int*   gid = (const int*)  d_in[1];
    const float* W1  = (const float*)d_in[2];
    const float* b1  = (const float*)d_in[3];
    const float* W2  = (const float*)d_in[4];
    const float* b2  = (const float*)d_in[5];
    const float* W3  = (const float*)d_in[6];
    float* out = (float*)d_out;

    __half *xf, *w1f, *w2f, *w3f, *sf, *h2f;
    cudaGetSymbolAddress((void**)&xf,  g_xf);
    cudaGetSymbolAddress((void**)&w1f, g_W1f);
    cudaGetSymbolAddress((void**)&w2f, g_W2f);
    cudaGetSymbolAddress((void**)&w3f, g_W3f);
    cudaGetSymbolAddress((void**)&sf,  g_sf);
    cudaGetSymbolAddress((void**)&h2f, g_h2f);

    cudaFuncSetAttribute((const void*)mma_gemm<true>,
                         cudaFuncAttributeMaxDynamicSharedMemorySize, SMEM_TOTAL);
    cudaFuncSetAttribute((const void*)mma_gemm<false>,
                         cudaFuncAttributeMaxDynamicSharedMemorySize, SMEM_TOTAL);

    sort_gates<<<1, 256>>>(gid);

    auto nblk = [](size_t elems) { return (int)((elems / 4 + 1023) / 1024); };
    conv_f32h<<<nblk((size_t)NROWS * INDIM), 256>>>(x, xf, NROWS * INDIM / 4);
    conv_f32h<<<nblk((size_t)W1R * INDIM),   256>>>(W1, w1f, (int)((size_t)W1R * INDIM / 4));
    conv_f32h<<<nblk((size_t)DDIM * TWOD),   256>>>(W2, w2f, DDIM * TWOD / 4);
    conv_f32h<<<nblk((size_t)OUTDIM * DDIM), 256>>>(W3, w3f, OUTDIM * DDIM / 4);

    // L1 gate blocks: s = 0.9*relu(x @ W1_g^T + b1_g), rows scattered via perm
    mma_gemm<true><<<dim3(TWOD / BN, NROWS / BM, NGATE), THREADS, SMEM_TOTAL>>>(
        xf, w1f, b1,
        nullptr, sf, nullptr,
        TWOD, INDIM, /*relu=*/1, /*scale=*/0.9f);

    // L1 shared block: s += relu(x @ W1_sh^T + b1_sh)
    mma_gemm<false><<<dim3(TWOD / BN, NROWS / BM), THREADS, SMEM_TOTAL>>>(
        xf,
        w1f + (size_t)NGATE * TWOD * INDIM,
        b1 + (size_t)NGATE * TWOD,
        nullptr, sf, sf,
        TWOD, INDIM, /*relu=*/1, /*scale=*/1.0f);

    // L2: h2 = relu(s @ W2^T + b2)
    mma_gemm<false><<<dim3(DDIM / BN, NROWS / BM), THREADS, SMEM_TOTAL>>>(
        sf, w2f, b2,
        nullptr, h2f, nullptr,
        DDIM, TWOD, /*relu=*/1, /*scale=*/1.0f);

    // L3: out = h2 @ W3^T  (fp32 store)
    mma_gemm<false><<<dim3(OUTDIM / BN, NROWS / BM), THREADS, SMEM_TOTAL>>>(
        h2f, w3f, nullptr,
        out, nullptr, nullptr,
        OUTDIM, DDIM, /*relu=*/0, /*scale=*/1.0f);
}